// round 2
// baseline (speedup 1.0000x reference)
#include <cuda_runtime.h>

// Problem constants
#define NN 1024
#define DD 64
#define RR 32
#define NEGV (-1e14f)

// Scratch / accumulators (no device allocation allowed)
__device__ float g_ewm[(size_t)NN * NN];
__device__ double g_sum;
__device__ double g_sumsq;
__device__ unsigned long long g_cnt;
__device__ float g_mean;
__device__ float g_invstd;

__global__ void k_zero() {
    g_sum = 0.0;
    g_sumsq = 0.0;
    g_cnt = 0ull;
}

// ewm[i,j] = sum_d grad[i,j,d] * rs[j,i,d]   (one warp per (i,j) pair)
// Also accumulates sum / sumsq / count over nonzero entries for the
// global normalization (torch.std, ddof=1).
__global__ void k_ewm(const float* __restrict__ grad,
                      const float* __restrict__ rs) {
    const int lane   = threadIdx.x & 31;
    const int wid    = (blockIdx.x * blockDim.x + threadIdx.x) >> 5;
    const int nwarps = (gridDim.x * blockDim.x) >> 5;

    double lsum = 0.0, lsumsq = 0.0;
    unsigned long long lcnt = 0ull;

    for (int p = wid; p < NN * NN; p += nwarps) {
        const int i = p >> 10;        // p / NN
        const int j = p & (NN - 1);   // p % NN

        const float2* ga = (const float2*)(grad + (size_t)p * DD);
        const float2* ra = (const float2*)(rs + (((size_t)j << 10) + i) * DD);

        float2 gv = ga[lane];
        float2 rv = ra[lane];
        float acc = gv.x * rv.x + gv.y * rv.y;

        #pragma unroll
        for (int off = 16; off > 0; off >>= 1)
            acc += __shfl_xor_sync(0xffffffffu, acc, off);

        if (lane == 0) {
            g_ewm[p] = acc;
            if (acc != 0.0f) {
                lsum   += (double)acc;
                lsumsq += (double)acc * (double)acc;
                lcnt   += 1ull;
            }
        }
    }

    if (lane == 0 && lcnt) {
        atomicAdd(&g_sum, lsum);
        atomicAdd(&g_sumsq, lsumsq);
        atomicAdd(&g_cnt, lcnt);
    }
}

__global__ void k_stats() {
    double c    = (double)g_cnt;
    double mean = g_sum / c;
    double var  = (g_sumsq - g_sum * g_sum / c) / (c - 1.0);
    g_mean   = (float)mean;
    g_invstd = (float)(1.0 / sqrt(var));
}

// Fused epilogue: per (i,j) pair (one warp, lane = relation index r):
//   g      = rmg * rm
//   res    = zero ? NEG : 2*(g - min)/(max - min) - 1     (max/min over r incl. zeros)
//   pres   = softmax_r(res) * rm
//   sig    = ewm==0 ? 0 : sigmoid((ewm - mean) * invstd)
//   out    = sig * pres
__global__ void k_out(const float* __restrict__ rm,
                      const float* __restrict__ rmg,
                      float* __restrict__ out) {
    const int lane   = threadIdx.x & 31;
    const int wid    = (blockIdx.x * blockDim.x + threadIdx.x) >> 5;
    const int nwarps = (gridDim.x * blockDim.x) >> 5;

    const float mean   = g_mean;
    const float invstd = g_invstd;

    for (int p = wid; p < NN * NN; p += nwarps) {
        const size_t base = (size_t)p * RR + lane;
        const float m  = rm[base];
        const float mg = rmg[base];
        const float g  = m * mg;
        const bool zero = (g == 0.0f);

        float mx = g, mn = g;
        #pragma unroll
        for (int off = 16; off > 0; off >>= 1) {
            mx = fmaxf(mx, __shfl_xor_sync(0xffffffffu, mx, off));
            mn = fminf(mn, __shfl_xor_sync(0xffffffffu, mn, off));
        }

        float res = zero ? NEGV : fmaf(2.0f, (g - mn) / (mx - mn), -1.0f);

        float rmax = res;
        #pragma unroll
        for (int off = 16; off > 0; off >>= 1)
            rmax = fmaxf(rmax, __shfl_xor_sync(0xffffffffu, rmax, off));

        // all-zero row: res = rmax = NEG -> e = exp(0) = 1, uniform softmax,
        // then * rm (=0) -> 0, matching the reference.
        float e = __expf(res - rmax);

        float s = e;
        #pragma unroll
        for (int off = 16; off > 0; off >>= 1)
            s += __shfl_xor_sync(0xffffffffu, s, off);

        const float pres = (e / s) * m;

        const float ew = g_ewm[p];
        float sig = 0.0f;
        if (ew != 0.0f)
            sig = 1.0f / (1.0f + __expf(-(ew - mean) * invstd));

        out[base] = sig * pres;
    }
}

extern "C" void kernel_launch(void* const* d_in, const int* in_sizes, int n_in,
                              void* d_out, int out_size) {
    const float* rs   = (const float*)d_in[0];  // relation_stocks [N,N,D]
    const float* grad = (const float*)d_in[1];  // grad            [N,N,D]
    const float* rm   = (const float*)d_in[2];  // relation_matrix [N,N,R]
    const float* rmg  = (const float*)d_in[3];  // relation_matrix_grad [N,N,R]
    float* out = (float*)d_out;                 // [N,N,R]

    (void)in_sizes; (void)n_in; (void)out_size;

    k_zero<<<1, 1>>>();
    k_ewm<<<8192, 256>>>(grad, rs);
    k_stats<<<1, 1>>>();
    k_out<<<8192, 256>>>(rm, rmg, out);
}

// round 6
// speedup vs baseline: 2.5036x; 2.5036x over previous
#include <cuda_runtime.h>

// Problem constants
#define NN 1024
#define DD 64
#define RR 32
#define NEGV (-1e14f)

// Scratch / accumulators (no device allocation allowed)
__device__ float g_ewm[(size_t)NN * NN];
__device__ double g_sum;
__device__ double g_sumsq;
__device__ unsigned long long g_cnt;
__device__ float g_mean;
__device__ float g_invstd;

__global__ void k_zero() {
    g_sum = 0.0;
    g_sumsq = 0.0;
    g_cnt = 0ull;
}

// ewm[i,j] = sum_d grad[i,j,d] * rs[j,i,d]
// Tiled: block = 16x16 pair tile (i0..i0+15, j0..j0+15) for DRAM locality on
// the transposed rs reads. 8 lanes per pair, float4 loads (fully coalesced:
// each warp instruction covers 4 pairs x 128B contiguous).
__global__ void k_ewm(const float* __restrict__ grad,
                      const float* __restrict__ rs) {
    __shared__ double s_sum[8], s_ss[8];
    __shared__ unsigned int s_cnt[8];

    const int tid  = threadIdx.x;
    const int w    = tid >> 5;
    const int lane = tid & 31;
    const int pg   = lane >> 3;   // pair within warp (0..3)
    const int sub  = lane & 7;    // chunk within pair (0..7)

    const int i0 = blockIdx.y << 4;
    const int j0 = blockIdx.x << 4;

    float ls = 0.0f, lss = 0.0f;
    unsigned int lc = 0u;

    #pragma unroll
    for (int t = 0; t < 8; ++t) {
        const int gidx = t * 8 + w;                 // 0..63 groups (4 pairs each)
        const int i  = i0 + (gidx >> 2);
        const int jb = j0 + ((gidx & 3) << 2);      // base j of this 4-pair group
        const int j  = jb + pg;

        const float4* ga = (const float4*)(grad + (((size_t)i << 10) + j) * DD);
        const float4* ra = (const float4*)(rs   + (((size_t)j << 10) + i) * DD);

        float4 g0 = ga[sub];
        float4 g1 = ga[sub + 8];
        float4 r0 = ra[sub];
        float4 r1 = ra[sub + 8];

        float acc = g0.x * r0.x + g0.y * r0.y + g0.z * r0.z + g0.w * r0.w
                  + g1.x * r1.x + g1.y * r1.y + g1.z * r1.z + g1.w * r1.w;

        // reduce over the 8 lanes of this pair
        acc += __shfl_xor_sync(0xffffffffu, acc, 4);
        acc += __shfl_xor_sync(0xffffffffu, acc, 2);
        acc += __shfl_xor_sync(0xffffffffu, acc, 1);

        // gather the 4 pair results (held at lanes 0,8,16,24) into lane 0
        float a0 = __shfl_sync(0xffffffffu, acc, 0);
        float a1 = __shfl_sync(0xffffffffu, acc, 8);
        float a2 = __shfl_sync(0xffffffffu, acc, 16);
        float a3 = __shfl_sync(0xffffffffu, acc, 24);
        if (lane == 0) {
            *(float4*)(g_ewm + ((size_t)i << 10) + jb) = make_float4(a0, a1, a2, a3);
        }

        if (sub == 0 && acc != 0.0f) {
            ls  += acc;
            lss += acc * acc;
            lc  += 1u;
        }
    }

    // warp reduce (only lanes with sub==0 carry data; others are zero)
    #pragma unroll
    for (int off = 16; off > 0; off >>= 1) {
        ls  += __shfl_xor_sync(0xffffffffu, ls, off);
        lss += __shfl_xor_sync(0xffffffffu, lss, off);
        lc  += __shfl_xor_sync(0xffffffffu, lc, off);
    }
    if (lane == 0) { s_sum[w] = (double)ls; s_ss[w] = (double)lss; s_cnt[w] = lc; }
    __syncthreads();
    if (tid == 0) {
        double bs = 0.0, bss = 0.0;
        unsigned int bc = 0u;
        #pragma unroll
        for (int k = 0; k < 8; ++k) { bs += s_sum[k]; bss += s_ss[k]; bc += s_cnt[k]; }
        if (bc) {
            atomicAdd(&g_sum, bs);
            atomicAdd(&g_sumsq, bss);
            atomicAdd(&g_cnt, (unsigned long long)bc);
        }
    }
}

__global__ void k_stats() {
    double c    = (double)g_cnt;
    double mean = g_sum / c;
    double var  = (g_sumsq - g_sum * g_sum / c) / (c - 1.0);
    g_mean   = (float)mean;
    g_invstd = (float)(1.0 / sqrt(var));
}

// Fused epilogue: 8 lanes per pair, float4 per lane (warp = 4 pairs, fully
// coalesced 512B per load instruction). Softmax without the max-subtraction
// pass: res in [-1,1] for nonzero entries (no overflow), masked entries
// contribute e=0 exactly; all-zero rows guarded via s==0 -> 0.
__global__ void k_out(const float* __restrict__ rm,
                      const float* __restrict__ rmg,
                      float* __restrict__ out) {
    const int lane = threadIdx.x & 31;
    const int pg   = lane >> 3;
    const int sub  = lane & 7;
    const int W    = (blockIdx.x * blockDim.x + threadIdx.x) >> 5;
    const int p    = W * 4 + pg;                    // pair index (exact cover)

    const size_t vbase = (size_t)p * (RR / 4) + sub;   // float4 index
    float4 m  = ((const float4*)rm)[vbase];
    float4 mg = ((const float4*)rmg)[vbase];

    float4 g = make_float4(m.x * mg.x, m.y * mg.y, m.z * mg.z, m.w * mg.w);

    float mx = fmaxf(fmaxf(g.x, g.y), fmaxf(g.z, g.w));
    float mn = fminf(fminf(g.x, g.y), fminf(g.z, g.w));
    #pragma unroll
    for (int off = 4; off > 0; off >>= 1) {
        mx = fmaxf(mx, __shfl_xor_sync(0xffffffffu, mx, off));
        mn = fminf(mn, __shfl_xor_sync(0xffffffffu, mn, off));
    }

    const float inv2 = 2.0f / (mx - mn);   // inf if all-zero; e's selected to 0 below

    float e0 = (g.x == 0.0f) ? 0.0f : __expf(fmaf(g.x - mn, inv2, -1.0f));
    float e1 = (g.y == 0.0f) ? 0.0f : __expf(fmaf(g.y - mn, inv2, -1.0f));
    float e2 = (g.z == 0.0f) ? 0.0f : __expf(fmaf(g.z - mn, inv2, -1.0f));
    float e3 = (g.w == 0.0f) ? 0.0f : __expf(fmaf(g.w - mn, inv2, -1.0f));

    float s = (e0 + e1) + (e2 + e3);
    #pragma unroll
    for (int off = 4; off > 0; off >>= 1)
        s += __shfl_xor_sync(0xffffffffu, s, off);

    const float invs = (s > 0.0f) ? (1.0f / s) : 0.0f;

    const float ew = g_ewm[p];
    float sig = 0.0f;
    if (ew != 0.0f)
        sig = 1.0f / (1.0f + __expf(-(ew - g_mean) * g_invstd));

    const float f = sig * invs;
    float4 o = make_float4(e0 * m.x * f, e1 * m.y * f, e2 * m.z * f, e3 * m.w * f);
    ((float4*)out)[vbase] = o;
}

extern "C" void kernel_launch(void* const* d_in, const int* in_sizes, int n_in,
                              void* d_out, int out_size) {
    const float* rs   = (const float*)d_in[0];  // relation_stocks [N,N,D]
    const float* grad = (const float*)d_in[1];  // grad            [N,N,D]
    const float* rm   = (const float*)d_in[2];  // relation_matrix [N,N,R]
    const float* rmg  = (const float*)d_in[3];  // relation_matrix_grad [N,N,R]
    float* out = (float*)d_out;                 // [N,N,R]

    (void)in_sizes; (void)n_in; (void)out_size;

    k_zero<<<1, 1>>>();
    k_ewm<<<dim3(64, 64), 256>>>(grad, rs);
    k_stats<<<1, 1>>>();
    // 1M pairs / (4 pairs/warp * 8 warps/block) = 32768 blocks
    k_out<<<32768, 256>>>(rm, rmg, out);
}

// round 11
// speedup vs baseline: 2.5567x; 1.0212x over previous
#include <cuda_runtime.h>

// Problem constants
#define NN 1024
#define DD 64
#define RR 32
#define NEGV (-1e14f)

// Scratch / accumulators (no device allocation allowed)
__device__ float g_ewm[(size_t)NN * NN];
__device__ double g_sum;
__device__ double g_sumsq;
__device__ unsigned long long g_cnt;
__device__ float g_mean;
__device__ float g_invstd;

__global__ void k_zero() {
    g_sum = 0.0;
    g_sumsq = 0.0;
    g_cnt = 0ull;
}

// ewm[i,j] = sum_d grad[i,j,d] * rs[j,i,d]
// Tiled: block = 16x16 pair tile (i0..i0+15, j0..j0+15) for DRAM locality on
// the transposed rs reads. 8 lanes per pair, float4 loads (fully coalesced:
// each warp instruction covers 4 pairs x 128B contiguous). Streaming loads
// (__ldcs) since every byte is touched exactly once.
__global__ void k_ewm(const float* __restrict__ grad,
                      const float* __restrict__ rs) {
    __shared__ double s_sum[8], s_ss[8];
    __shared__ unsigned int s_cnt[8];

    const int tid  = threadIdx.x;
    const int w    = tid >> 5;
    const int lane = tid & 31;
    const int pg   = lane >> 3;   // pair within warp (0..3)
    const int sub  = lane & 7;    // chunk within pair (0..7)

    const int i0 = blockIdx.y << 4;
    const int j0 = blockIdx.x << 4;

    float ls = 0.0f, lss = 0.0f;
    unsigned int lc = 0u;

    #pragma unroll
    for (int t = 0; t < 8; ++t) {
        const int gidx = t * 8 + w;                 // 0..63 groups (4 pairs each)
        const int i  = i0 + (gidx >> 2);
        const int jb = j0 + ((gidx & 3) << 2);      // base j of this 4-pair group
        const int j  = jb + pg;

        const float4* ga = (const float4*)(grad + (((size_t)i << 10) + j) * DD);
        const float4* ra = (const float4*)(rs   + (((size_t)j << 10) + i) * DD);

        float4 g0 = __ldcs(ga + sub);
        float4 g1 = __ldcs(ga + sub + 8);
        float4 r0 = __ldcs(ra + sub);
        float4 r1 = __ldcs(ra + sub + 8);

        float acc = g0.x * r0.x + g0.y * r0.y + g0.z * r0.z + g0.w * r0.w
                  + g1.x * r1.x + g1.y * r1.y + g1.z * r1.z + g1.w * r1.w;

        // reduce over the 8 lanes of this pair
        acc += __shfl_xor_sync(0xffffffffu, acc, 4);
        acc += __shfl_xor_sync(0xffffffffu, acc, 2);
        acc += __shfl_xor_sync(0xffffffffu, acc, 1);

        // gather the 4 pair results (held at lanes 0,8,16,24) into lane 0
        float a0 = __shfl_sync(0xffffffffu, acc, 0);
        float a1 = __shfl_sync(0xffffffffu, acc, 8);
        float a2 = __shfl_sync(0xffffffffu, acc, 16);
        float a3 = __shfl_sync(0xffffffffu, acc, 24);
        if (lane == 0) {
            *(float4*)(g_ewm + ((size_t)i << 10) + jb) = make_float4(a0, a1, a2, a3);
        }

        if (sub == 0 && acc != 0.0f) {
            ls  += acc;
            lss += acc * acc;
            lc  += 1u;
        }
    }

    // warp reduce (only lanes with sub==0 carry data; others are zero)
    #pragma unroll
    for (int off = 16; off > 0; off >>= 1) {
        ls  += __shfl_xor_sync(0xffffffffu, ls, off);
        lss += __shfl_xor_sync(0xffffffffu, lss, off);
        lc  += __shfl_xor_sync(0xffffffffu, lc, off);
    }
    if (lane == 0) { s_sum[w] = (double)ls; s_ss[w] = (double)lss; s_cnt[w] = lc; }
    __syncthreads();
    if (tid == 0) {
        double bs = 0.0, bss = 0.0;
        unsigned int bc = 0u;
        #pragma unroll
        for (int k = 0; k < 8; ++k) { bs += s_sum[k]; bss += s_ss[k]; bc += s_cnt[k]; }
        if (bc) {
            atomicAdd(&g_sum, bs);
            atomicAdd(&g_sumsq, bss);
            atomicAdd(&g_cnt, (unsigned long long)bc);
        }
    }
}

__global__ void k_stats() {
    double c    = (double)g_cnt;
    double mean = g_sum / c;
    double var  = (g_sumsq - g_sum * g_sum / c) / (c - 1.0);
    g_mean   = (float)mean;
    g_invstd = (float)(1.0 / sqrt(var));
}

// Softmax/scale for one 4-value slice of a pair. 8-lane-group reductions.
__device__ __forceinline__ void out_pair(float4 m, float4 mg, float ew,
                                         float mean, float invstd,
                                         float4& o) {
    float4 g = make_float4(m.x * mg.x, m.y * mg.y, m.z * mg.z, m.w * mg.w);

    float mx = fmaxf(fmaxf(g.x, g.y), fmaxf(g.z, g.w));
    float mn = fminf(fminf(g.x, g.y), fminf(g.z, g.w));
    #pragma unroll
    for (int off = 4; off > 0; off >>= 1) {
        mx = fmaxf(mx, __shfl_xor_sync(0xffffffffu, mx, off));
        mn = fminf(mn, __shfl_xor_sync(0xffffffffu, mn, off));
    }

    const float inv2 = 2.0f / (mx - mn);   // inf if all-zero; e's selected to 0 below

    float e0 = (g.x == 0.0f) ? 0.0f : __expf(fmaf(g.x - mn, inv2, -1.0f));
    float e1 = (g.y == 0.0f) ? 0.0f : __expf(fmaf(g.y - mn, inv2, -1.0f));
    float e2 = (g.z == 0.0f) ? 0.0f : __expf(fmaf(g.z - mn, inv2, -1.0f));
    float e3 = (g.w == 0.0f) ? 0.0f : __expf(fmaf(g.w - mn, inv2, -1.0f));

    float s = (e0 + e1) + (e2 + e3);
    #pragma unroll
    for (int off = 4; off > 0; off >>= 1)
        s += __shfl_xor_sync(0xffffffffu, s, off);

    const float invs = (s > 0.0f) ? (1.0f / s) : 0.0f;

    float sig = 0.0f;
    if (ew != 0.0f)
        sig = 1.0f / (1.0f + __expf(-(ew - mean) * invstd));

    const float f = sig * invs;
    o = make_float4(e0 * m.x * f, e1 * m.y * f, e2 * m.z * f, e3 * m.w * f);
}

// Fused epilogue: each warp handles 8 pairs as two independent 512B-contiguous
// float4 sets, loaded back-to-back before compute for doubled MLP.
__global__ void k_out(const float* __restrict__ rm,
                      const float* __restrict__ rmg,
                      float* __restrict__ out) {
    const int lane = threadIdx.x & 31;
    const int pg   = lane >> 3;
    const int W    = (blockIdx.x * blockDim.x + threadIdx.x) >> 5;

    const size_t b0 = (size_t)W * 64 + lane;   // float4 idx, set A (pairs 8W..8W+3)
    const size_t b1 = b0 + 32;                 // set B (pairs 8W+4..8W+7)
    const int pA = W * 8 + pg;
    const int pB = pA + 4;

    // issue all loads first (MLP)
    float4 mA  = __ldcs(((const float4*)rm)  + b0);
    float4 gA  = __ldcs(((const float4*)rmg) + b0);
    float4 mB  = __ldcs(((const float4*)rm)  + b1);
    float4 gB  = __ldcs(((const float4*)rmg) + b1);
    float ewA = g_ewm[pA];
    float ewB = g_ewm[pB];

    const float mean   = g_mean;
    const float invstd = g_invstd;

    float4 oA, oB;
    out_pair(mA, gA, ewA, mean, invstd, oA);
    out_pair(mB, gB, ewB, mean, invstd, oB);

    __stcs(((float4*)out) + b0, oA);
    __stcs(((float4*)out) + b1, oB);
}

extern "C" void kernel_launch(void* const* d_in, const int* in_sizes, int n_in,
                              void* d_out, int out_size) {
    const float* rs   = (const float*)d_in[0];  // relation_stocks [N,N,D]
    const float* grad = (const float*)d_in[1];  // grad            [N,N,D]
    const float* rm   = (const float*)d_in[2];  // relation_matrix [N,N,R]
    const float* rmg  = (const float*)d_in[3];  // relation_matrix_grad [N,N,R]
    float* out = (float*)d_out;                 // [N,N,R]

    (void)in_sizes; (void)n_in; (void)out_size;

    k_zero<<<1, 1>>>();
    k_ewm<<<dim3(64, 64), 256>>>(grad, rs);
    k_stats<<<1, 1>>>();
    // 1M pairs / (8 pairs/warp * 8 warps/block) = 16384 blocks
    k_out<<<16384, 256>>>(rm, rmg, out);
}